// round 14
// baseline (speedup 1.0000x reference)
#include <cuda_runtime.h>
#include <math.h>
#include <stdint.h>

// Problem constants
#define BB   2
#define SS   2048
#define HH   2048
#define NHH  16
#define HD   128
#define MR   (BB*SS)        // 4096 rows

// ---------------- scratch (device globals; no allocation allowed) ----------
__device__ float g_ln [(size_t)MR * HH];
__device__ float g_qkv[(size_t)MR * 3 * HH];
__device__ float g_av [(size_t)MR * HH];
__device__ float g_h  [(size_t)MR * HH];
__device__ float g_mid[(size_t)MR * 4 * HH];
__device__ float g_wr [(size_t)12 * HH * HH];   // tf32-rounded weights

// ---------------- helpers ---------------------------------------------------
__device__ __forceinline__ uint32_t f2tf32(float f) {
    uint32_t u;
    asm("cvt.rna.tf32.f32 %0, %1;" : "=r"(u) : "f"(f));
    return u;
}
__device__ __forceinline__ float roundtf(float f) {
    return __uint_as_float(f2tf32(f));
}
__device__ __forceinline__ uint32_t smem_u32(const void* p) {
    uint32_t a;
    asm("{ .reg .u64 t; cvta.to.shared.u64 t, %1; cvt.u32.u64 %0, t; }" : "=r"(a) : "l"(p));
    return a;
}
__device__ __forceinline__ void cp_async16(uint32_t dst, const void* src) {
    asm volatile("cp.async.cg.shared.global [%0], [%1], 16;" :: "r"(dst), "l"(src));
}
#define CP_COMMIT() asm volatile("cp.async.commit_group;" ::: "memory")
#define CP_WAIT1()  asm volatile("cp.async.wait_group 1;"  ::: "memory")
#define CP_WAIT0()  asm volatile("cp.async.wait_group 0;"  ::: "memory")

// mma.sync m16n8k8 tf32: D = A*B + D
__device__ __forceinline__ void mma_tf32(float c[4],
                                         uint32_t a0, uint32_t a1, uint32_t a2, uint32_t a3,
                                         uint32_t b0, uint32_t b1) {
    asm volatile(
        "mma.sync.aligned.m16n8k8.row.col.f32.tf32.tf32.f32 "
        "{%0,%1,%2,%3}, {%4,%5,%6,%7}, {%8,%9}, {%0,%1,%2,%3};"
        : "+f"(c[0]), "+f"(c[1]), "+f"(c[2]), "+f"(c[3])
        : "r"(a0), "r"(a1), "r"(a2), "r"(a3), "r"(b0), "r"(b1));
}

// ---------------- weight rounding (single launch, all 4 weights) -----------
// g_wr layout: [wqkv 3H^2 | wo H^2 | w1 4H^2 | w2 4H^2]
__global__ void round_all_kernel(const float4* __restrict__ wqkv,
                                 const float4* __restrict__ wo,
                                 const float4* __restrict__ w1,
                                 const float4* __restrict__ w2,
                                 float4* __restrict__ out)
{
    const int n4q = 3 * HH * (HH / 4);
    const int n4o = HH * (HH / 4);
    const int n4m = HH * HH;           // 4*H*H/4
    int i = blockIdx.x * blockDim.x + threadIdx.x;
    float4 v;
    if (i < n4q)                        v = wqkv[i];
    else if (i < n4q + n4o)             v = wo[i - n4q];
    else if (i < n4q + n4o + n4m)       v = w1[i - n4q - n4o];
    else                                v = w2[i - n4q - n4o - n4m];
    out[i] = make_float4(roundtf(v.x), roundtf(v.y), roundtf(v.z), roundtf(v.w));
}

// ======================= tf32 mma.sync GEMM (cp.async) =====================
// C[M,N] = A[M,K] @ W[N,K]^T + bias
// EPI: 0 bias+tf32round, 1 +res, 2 exact GELU + tf32round
#define KC          32
#define STG_FLOATS  8192
#define NSTAGE      3
#define GEMM_SMEM_BYTES (NSTAGE * STG_FLOATS * 4)   // 98304

template<int EPI>
__global__ void __launch_bounds__(256, 2)
gemm_cp(const float* __restrict__ A, const float* __restrict__ W,
        const float* __restrict__ bias, const float* __restrict__ res,
        float* __restrict__ C, int M, int N, int K)
{
    extern __shared__ float sm[];
    const uint32_t sbase = smem_u32(sm);
    const int t    = threadIdx.x;
    const int lane = t & 31;
    const int wid  = t >> 5;
    const int warp_m = wid >> 2;
    const int warp_n = wid & 3;
    const int m0 = blockIdx.y * 128;
    const int n0 = blockIdx.x * 128;

    const float* Ap = A + (size_t)m0 * K;
    const float* Wp = W + (size_t)n0 * K;

    const int cprow = t >> 3;
    const int cpc16 = t & 7;
    const int cpswz = (cpc16 ^ (cprow & 7)) * 4;

    const int g = lane >> 2;
    const int j = lane & 3;

    float acc[4][4][4];
    #pragma unroll
    for (int m = 0; m < 4; m++)
        #pragma unroll
        for (int n = 0; n < 4; n++)
            #pragma unroll
            for (int r = 0; r < 4; r++) acc[m][n][r] = 0.f;

    auto ISSUE = [&](int ch, int stage) {
        const int k0 = ch * KC;
        const uint32_t so = sbase + (uint32_t)stage * (STG_FLOATS * 4);
        #pragma unroll
        for (int i = 0; i < 4; i++) {
            const int row = cprow + i * 32;
            cp_async16(so + (uint32_t)(row * 32 + cpswz) * 4u,
                       Ap + (size_t)row * K + k0 + cpc16 * 4);
        }
        #pragma unroll
        for (int i = 0; i < 4; i++) {
            const int row = cprow + i * 32;
            cp_async16(so + (uint32_t)(4096 + row * 32 + cpswz) * 4u,
                       Wp + (size_t)row * K + k0 + cpc16 * 4);
        }
        CP_COMMIT();
    };

    auto CONSUME = [&](int stage) {
        const float* sA = sm + stage * STG_FLOATS;
        const float* sB = sA + 4096;
        #pragma unroll
        for (int kk = 0; kk < 4; kk++) {
            uint32_t af[4][4];
            uint32_t bf[4][2];
            #pragma unroll
            for (int m = 0; m < 4; m++) {
                const int rbase = warp_m * 64 + m * 16 + g;
                #pragma unroll
                for (int r = 0; r < 4; r++) {
                    const int row = rbase + (r & 1) * 8;
                    const int col = (((kk * 2 + (r >> 1)) ^ g) * 4) + j;
                    af[m][r] = __float_as_uint(sA[row * 32 + col]);
                }
            }
            #pragma unroll
            for (int n = 0; n < 4; n++) {
                const int nrow = warp_n * 32 + n * 8 + g;
                #pragma unroll
                for (int r = 0; r < 2; r++) {
                    const int col = (((kk * 2 + r) ^ g) * 4) + j;
                    bf[n][r] = __float_as_uint(sB[nrow * 32 + col]);
                }
            }
            #pragma unroll
            for (int m = 0; m < 4; m++)
                #pragma unroll
                for (int n = 0; n < 4; n++)
                    mma_tf32(acc[m][n], af[m][0], af[m][1], af[m][2], af[m][3],
                             bf[n][0], bf[n][1]);
        }
    };

    const int nch = K >> 5;
    ISSUE(0, 0);
    ISSUE(1, 1);
    int stage = 0;
    for (int ch = 0; ch < nch; ch++) {
        CP_WAIT1();
        __syncthreads();
        CONSUME(stage);
        if (ch + 2 < nch) {
            int ns = stage + 2; if (ns >= NSTAGE) ns -= NSTAGE;
            ISSUE(ch + 2, ns);
        } else {
            CP_COMMIT();
        }
        stage = (stage + 1 == NSTAGE) ? 0 : stage + 1;
    }

    const int gid = lane >> 2;
    const int tig = lane & 3;
    #pragma unroll
    for (int n = 0; n < 4; n++) {
        const int col = n0 + (warp_n * 4 + n) * 8 + tig * 2;
        const float2 bv = *(const float2*)&bias[col];
        #pragma unroll
        for (int m = 0; m < 4; m++) {
            const int rowa = m0 + (warp_m * 4 + m) * 16 + gid;
            const size_t offa = (size_t)rowa * N + col;
            const size_t offb = offa + (size_t)8 * N;
            float o0 = acc[m][n][0] + bv.x;
            float o1 = acc[m][n][1] + bv.y;
            float o2 = acc[m][n][2] + bv.x;
            float o3 = acc[m][n][3] + bv.y;
            if (EPI == 1) {
                float2 r0 = *(const float2*)&res[offa];
                float2 r1 = *(const float2*)&res[offb];
                o0 += r0.x; o1 += r0.y; o2 += r1.x; o3 += r1.y;
            }
            if (EPI == 2) {
                o0 = 0.5f * o0 * (1.0f + erff(o0 * 0.70710678118654752f));
                o1 = 0.5f * o1 * (1.0f + erff(o1 * 0.70710678118654752f));
                o2 = 0.5f * o2 * (1.0f + erff(o2 * 0.70710678118654752f));
                o3 = 0.5f * o3 * (1.0f + erff(o3 * 0.70710678118654752f));
            }
            if (EPI == 0 || EPI == 2) {   // output feeds a GEMM/attention: pre-round
                o0 = roundtf(o0); o1 = roundtf(o1);
                o2 = roundtf(o2); o3 = roundtf(o3);
            }
            *(float2*)&C[offa] = make_float2(o0, o1);
            *(float2*)&C[offb] = make_float2(o2, o3);
        }
    }
}

// ---------------- LayerNorm (stores tf32-rounded; feeds GEMMs only) --------
__global__ void ln_kernel(const float* __restrict__ x,
                          const float* __restrict__ w,
                          const float* __restrict__ b,
                          float* __restrict__ y)
{
    const int row = blockIdx.x;
    const float* xr = x + (size_t)row * HH;
    float* yr = y + (size_t)row * HH;
    const int t = threadIdx.x;

    __shared__ float red[8];
    __shared__ float bc;

    float s = 0.f;
    for (int i = t; i < HH; i += 256) s += xr[i];
    #pragma unroll
    for (int o = 16; o; o >>= 1) s += __shfl_xor_sync(0xffffffffu, s, o);
    if ((t & 31) == 0) red[t >> 5] = s;
    __syncthreads();
    if (t == 0) {
        float v = 0.f;
        #pragma unroll
        for (int i = 0; i < 8; i++) v += red[i];
        bc = v;
    }
    __syncthreads();
    const float mu = bc * (1.0f / HH);

    float vs = 0.f;
    for (int i = t; i < HH; i += 256) { float d = xr[i] - mu; vs += d * d; }
    #pragma unroll
    for (int o = 16; o; o >>= 1) vs += __shfl_xor_sync(0xffffffffu, vs, o);
    __syncthreads();
    if ((t & 31) == 0) red[t >> 5] = vs;
    __syncthreads();
    if (t == 0) {
        float v = 0.f;
        #pragma unroll
        for (int i = 0; i < 8; i++) v += red[i];
        bc = v;
    }
    __syncthreads();
    const float rstd = rsqrtf(bc * (1.0f / HH) + 1e-5f);

    for (int i = t; i < HH; i += 256)
        yr[i] = roundtf((xr[i] - mu) * rstd * w[i] + b[i]);
}

// ======================= tensor-core flash attention ========================
// grid (S/128 [reversed], B*NH), 256 threads = 8 warps x 16 q-rows.
// smem (floats): sQ 16384 (4x4096) | sK 8192 (4x2048) | sVR 8192 (4x2048)
//              | sVT 8192 (2x4096) | sP 8192 (2x4096)  = 192 KB
// K and V loaded via cp.async (coalesced); V transposed smem->smem.
#define SQ_OFF  0
#define SK_OFF  16384
#define SVR_OFF 24576
#define SVT_OFF 32768
#define SP_OFF  40960
#define ATTN_SMEM_BYTES (49152 * 4)

__global__ void __launch_bounds__(256, 1)
attn_mma_kernel(const float* __restrict__ qkv, float* __restrict__ av)
{
    extern __shared__ float sma[];
    const uint32_t sabase = smem_u32(sma);
    const int t    = threadIdx.x;
    const int lane = t & 31;
    const int wid  = t >> 5;
    const int g    = lane >> 2;
    const int j    = lane & 3;

    const int qt = (gridDim.x - 1) - blockIdx.x;   // big tiles first
    const int bh = blockIdx.y;
    const int b  = bh >> 4;
    const int h  = bh & 15;
    const int qbase = qt * 128;

    const size_t rstr = (size_t)3 * HH;
    const float* base = qkv + (size_t)b * SS * rstr;
    const int qoff = h * HD;
    const int koff = HH + h * HD;
    const int voff = 2 * HH + h * HD;

    // ---- load Q tile (128x128) into 4 swizzled chunks (4096 floats each) ----
    #pragma unroll
    for (int i = 0; i < 16; i++) {
        const int idx = t + i * 256;           // 0..4095
        const int row = idx >> 5;
        const int c4  = idx & 31;
        float4 v = *(const float4*)(base + (size_t)(qbase + row) * rstr + qoff + c4 * 4);
        const int dst = SQ_OFF + (c4 >> 3) * 4096 + row * 32 + (((c4 & 7) ^ (row & 7)) * 4);
        *(float4*)&sma[dst] = v;
    }

    const int rloc0 = wid * 16 + g;
    const int qrow0 = qbase + rloc0;
    float m0 = -1e30f, m1 = -1e30f, l0 = 0.f, l1 = 0.f;
    float o[16][4];
    #pragma unroll
    for (int n = 0; n < 16; n++)
        #pragma unroll
        for (int r = 0; r < 4; r++) o[n][r] = 0.f;

    const float rsd = 0.08838834764831845f;   // 1/sqrt(128)
    const int nkt = 2 * (qt + 1);

    for (int kt = 0; kt < nkt; kt++) {
        const int kbase = kt * 64;
        __syncthreads();   // prior tile's reads of sK/sVT/sP done; Q stores (iter 0)

        // ---- cp.async K and V (both 64x128, k-major, 4 chunks of 2048) ----
        #pragma unroll
        for (int i = 0; i < 8; i++) {
            const int idx = t + i * 256;       // 0..2047
            const int row = idx >> 5;
            const int c4  = idx & 31;
            const int off = (c4 >> 3) * 2048 + row * 32 + (((c4 & 7) ^ (row & 7)) * 4);
            const float* srcrow = base + (size_t)(kbase + row) * rstr;
            cp_async16(sabase + (uint32_t)(SK_OFF  + off) * 4u, srcrow + koff + c4 * 4);
            cp_async16(sabase + (uint32_t)(SVR_OFF + off) * 4u, srcrow + voff + c4 * 4);
        }
        CP_COMMIT();
        CP_WAIT0();
        __syncthreads();

        // ---- transpose V: sVR[k][d] -> sVT[d][k] (swizzled both sides) ----
        #pragma unroll
        for (int i = 0; i < 32; i++) {
            const int k = (lane & 3) + 4 * (i & 7) + 32 * (wid & 1);
            const int d = (lane >> 2) + 8 * (i >> 3) + 32 * (wid >> 1);
            const float v = sma[SVR_OFF + (d >> 5) * 2048 + k * 32 +
                                ((((d >> 2) & 7) ^ (k & 7)) * 4) + (d & 3)];
            const int kc = k & 31;
            sma[SVT_OFF + (k >> 5) * 4096 + d * 32 + (((kc >> 2) ^ (d & 7)) * 4) + (kc & 3)] = v;
        }

        // ---- S = Q K^T : 8 n-atoms, 16 kk steps ----
        float s[8][4];
        #pragma unroll
        for (int n = 0; n < 8; n++)
            #pragma unroll
            for (int r = 0; r < 4; r++) s[n][r] = 0.f;

        #pragma unroll
        for (int kk = 0; kk < 16; kk++) {
            const int chunk = kk >> 2, kkl = kk & 3;
            uint32_t af[4];
            #pragma unroll
            for (int r = 0; r < 4; r++) {
                const int row = rloc0 + (r & 1) * 8;
                const int col = (((kkl * 2 + (r >> 1)) ^ g) * 4) + j;
                af[r] = __float_as_uint(sma[SQ_OFF + chunk * 4096 + row * 32 + col]);
            }
            #pragma unroll
            for (int n = 0; n < 8; n++) {
                uint32_t bf[2];
                #pragma unroll
                for (int r = 0; r < 2; r++) {
                    const int col = (((kkl * 2 + r) ^ g) * 4) + j;
                    bf[r] = __float_as_uint(sma[SK_OFF + chunk * 2048 + (n * 8 + g) * 32 + col]);
                }
                mma_tf32(s[n], af[0], af[1], af[2], af[3], bf[0], bf[1]);
            }
        }

        // ---- scale + causal mask + online softmax ----
        float tm0 = -1e30f, tm1 = -1e30f;
        #pragma unroll
        for (int n = 0; n < 8; n++) {
            #pragma unroll
            for (int e = 0; e < 2; e++) {
                const int col = kbase + n * 8 + j * 2 + e;
                float v0 = s[n][e]     * rsd; if (col > qrow0)     v0 -= 1e4f;
                float v1 = s[n][2 + e] * rsd; if (col > qrow0 + 8) v1 -= 1e4f;
                s[n][e] = v0; s[n][2 + e] = v1;
                tm0 = fmaxf(tm0, v0); tm1 = fmaxf(tm1, v1);
            }
        }
        tm0 = fmaxf(tm0, __shfl_xor_sync(0xffffffffu, tm0, 1));
        tm0 = fmaxf(tm0, __shfl_xor_sync(0xffffffffu, tm0, 2));
        tm1 = fmaxf(tm1, __shfl_xor_sync(0xffffffffu, tm1, 1));
        tm1 = fmaxf(tm1, __shfl_xor_sync(0xffffffffu, tm1, 2));

        const float nm0 = fmaxf(m0, tm0), nm1 = fmaxf(m1, tm1);
        const float f0 = __expf(m0 - nm0), f1 = __expf(m1 - nm1);
        m0 = nm0; m1 = nm1;

        float rs0 = 0.f, rs1 = 0.f;
        #pragma unroll
        for (int n = 0; n < 8; n++) {
            #pragma unroll
            for (int e = 0; e < 2; e++) {
                float p0 = __expf(s[n][e]     - nm0);
                float p1 = __expf(s[n][2 + e] - nm1);
                rs0 += p0; rs1 += p1;
                s[n][e] = p0; s[n][2 + e] = p1;
            }
        }
        rs0 += __shfl_xor_sync(0xffffffffu, rs0, 1);
        rs0 += __shfl_xor_sync(0xffffffffu, rs0, 2);
        rs1 += __shfl_xor_sync(0xffffffffu, rs1, 1);
        rs1 += __shfl_xor_sync(0xffffffffu, rs1, 2);
        l0 = l0 * f0 + rs0;
        l1 = l1 * f1 + rs1;

        #pragma unroll
        for (int n = 0; n < 16; n++) {
            o[n][0] *= f0; o[n][1] *= f0;
            o[n][2] *= f1; o[n][3] *= f1;
        }

        // ---- store P (rounded) into swizzled A-tile layout ----
        #pragma unroll
        for (int n = 0; n < 8; n++) {
            #pragma unroll
            for (int e = 0; e < 2; e++) {
                const int c  = n * 8 + j * 2 + e;
                const int kc = c & 31;
                const int so = SP_OFF + (c >> 5) * 4096 + (((kc >> 2) ^ g) * 4) + (kc & 3);
                sma[so + rloc0 * 32]       = roundtf(s[n][e]);
                sma[so + (rloc0 + 8) * 32] = roundtf(s[n][2 + e]);
            }
        }
        __syncthreads();   // publish P and VT before PV

        // ---- O += P V : 16 n-atoms (d), 8 kk steps (k) ----
        #pragma unroll
        for (int kk = 0; kk < 8; kk++) {
            const int chunk = kk >> 2, kkl = kk & 3;
            uint32_t af[4];
            #pragma unroll
            for (int r = 0; r < 4; r++) {
                const int row = rloc0 + (r & 1) * 8;
                const int col = (((kkl * 2 + (r >> 1)) ^ g) * 4) + j;
                af[r] = __float_as_uint(sma[SP_OFF + chunk * 4096 + row * 32 + col]);
            }
            #pragma unroll
            for (int n = 0; n < 16; n++) {
                uint32_t bf[2];
                #pragma unroll
                for (int r = 0; r < 2; r++) {
                    const int col = (((kkl * 2 + r) ^ g) * 4) + j;
                    bf[r] = __float_as_uint(sma[SVT_OFF + chunk * 4096 + (n * 8 + g) * 32 + col]);
                }
                mma_tf32(o[n], af[0], af[1], af[2], af[3], bf[0], bf[1]);
            }
        }
    }

    // ---- epilogue: normalize, round (feeds Wo GEMM), store ----
    const float inv0 = 1.0f / l0, inv1 = 1.0f / l1;
    #pragma unroll
    for (int n = 0; n < 16; n++) {
        const int col = h * HD + n * 8 + j * 2;
        float* p0 = av + (size_t)(b * SS + qrow0) * HH + col;
        float* p1 = av + (size_t)(b * SS + qrow0 + 8) * HH + col;
        *(float2*)p0 = make_float2(roundtf(o[n][0] * inv0), roundtf(o[n][1] * inv0));
        *(float2*)p1 = make_float2(roundtf(o[n][2] * inv1), roundtf(o[n][3] * inv1));
    }
}

// ---------------- launcher --------------------------------------------------
extern "C" void kernel_launch(void* const* d_in, const int* in_sizes, int n_in,
                              void* d_out, int out_size)
{
    const float* x      = (const float*)d_in[0];
    const float* ln1_w  = (const float*)d_in[1];
    const float* ln1_b  = (const float*)d_in[2];
    const float* wqkv_w = (const float*)d_in[3];
    const float* wqkv_b = (const float*)d_in[4];
    const float* wo_w   = (const float*)d_in[5];
    const float* wo_b   = (const float*)d_in[6];
    const float* ln2_w  = (const float*)d_in[7];
    const float* ln2_b  = (const float*)d_in[8];
    const float* w1     = (const float*)d_in[9];
    const float* b1     = (const float*)d_in[10];
    const float* w2     = (const float*)d_in[11];
    const float* b2     = (const float*)d_in[12];
    float* out = (float*)d_out;

    float *ln, *qkv, *av, *h, *mid, *wr;
    cudaGetSymbolAddress((void**)&ln,  g_ln);
    cudaGetSymbolAddress((void**)&qkv, g_qkv);
    cudaGetSymbolAddress((void**)&av,  g_av);
    cudaGetSymbolAddress((void**)&h,   g_h);
    cudaGetSymbolAddress((void**)&mid, g_mid);
    cudaGetSymbolAddress((void**)&wr,  g_wr);

    float* wqkv_r = wr;
    float* wo_r   = wr + (size_t)3 * HH * HH;
    float* w1_r   = wr + (size_t)4 * HH * HH;
    float* w2_r   = wr + (size_t)8 * HH * HH;

    cudaFuncSetAttribute(attn_mma_kernel,
                         cudaFuncAttributeMaxDynamicSharedMemorySize, ATTN_SMEM_BYTES);
    cudaFuncSetAttribute(gemm_cp<0>,
                         cudaFuncAttributeMaxDynamicSharedMemorySize, GEMM_SMEM_BYTES);
    cudaFuncSetAttribute(gemm_cp<1>,
                         cudaFuncAttributeMaxDynamicSharedMemorySize, GEMM_SMEM_BYTES);
    cudaFuncSetAttribute(gemm_cp<2>,
                         cudaFuncAttributeMaxDynamicSharedMemorySize, GEMM_SMEM_BYTES);

    // 0. round all weights to tf32 in one launch (mma truncation exact)
    {
        int n4 = 12 * HH * (HH / 4);
        round_all_kernel<<<n4 / 256, 256>>>((const float4*)wqkv_w, (const float4*)wo_w,
                                            (const float4*)w1, (const float4*)w2,
                                            (float4*)wr);
    }

    // 1. ln1(x)
    ln_kernel<<<MR, 256>>>(x, ln1_w, ln1_b, ln);
    // 2. qkv = ln @ Wqkv^T + b   (rounded for attention mma)
    gemm_cp<0><<<dim3(3*HH/128, MR/128), 256, GEMM_SMEM_BYTES>>>(ln, wqkv_r, wqkv_b, nullptr, qkv,
                                                                 MR, 3*HH, HH);
    // 3. av = attention(qkv)   (tensor-core flash, rounded output)
    attn_mma_kernel<<<dim3(SS/128, BB*NHH), 256, ATTN_SMEM_BYTES>>>(qkv, av);
    // 4. h = x + av @ Wo^T + b
    gemm_cp<1><<<dim3(HH/128, MR/128), 256, GEMM_SMEM_BYTES>>>(av, wo_r, wo_b, x, h,
                                                               MR, HH, HH);
    // 5. ln2(h)
    ln_kernel<<<MR, 256>>>(h, ln2_w, ln2_b, ln);
    // 6. mid = gelu(ln @ W1^T + b1)  (rounded)
    gemm_cp<2><<<dim3(4*HH/128, MR/128), 256, GEMM_SMEM_BYTES>>>(ln, w1_r, b1, nullptr, mid,
                                                                 MR, 4*HH, HH);
    // 7. out = h + mid @ W2^T + b2
    gemm_cp<1><<<dim3(HH/128, MR/128), 256, GEMM_SMEM_BYTES>>>(mid, w2_r, b2, h, out,
                                                               MR, HH, 4*HH);
}

// round 15
// speedup vs baseline: 1.0006x; 1.0006x over previous
#include <cuda_runtime.h>
#include <math.h>
#include <stdint.h>

// Problem constants
#define BB   2
#define SS   2048
#define HH   2048
#define NHH  16
#define HD   128
#define MR   (BB*SS)        // 4096 rows

// ---------------- scratch (device globals; no allocation allowed) ----------
__device__ float g_ln [(size_t)MR * HH];
__device__ float g_qkv[(size_t)MR * 3 * HH];
__device__ float g_av [(size_t)MR * HH];
__device__ float g_h  [(size_t)MR * HH];
__device__ float g_mid[(size_t)MR * 4 * HH];
__device__ float g_wr [(size_t)12 * HH * HH];   // tf32-rounded weights

// ---------------- helpers ---------------------------------------------------
__device__ __forceinline__ uint32_t f2tf32(float f) {
    uint32_t u;
    asm("cvt.rna.tf32.f32 %0, %1;" : "=r"(u) : "f"(f));
    return u;
}
__device__ __forceinline__ float roundtf(float f) {
    return __uint_as_float(f2tf32(f));
}
__device__ __forceinline__ uint32_t smem_u32(const void* p) {
    uint32_t a;
    asm("{ .reg .u64 t; cvta.to.shared.u64 t, %1; cvt.u32.u64 %0, t; }" : "=r"(a) : "l"(p));
    return a;
}
__device__ __forceinline__ void cp_async16(uint32_t dst, const void* src) {
    asm volatile("cp.async.cg.shared.global [%0], [%1], 16;" :: "r"(dst), "l"(src));
}
#define CP_COMMIT() asm volatile("cp.async.commit_group;" ::: "memory")
#define CP_WAIT1()  asm volatile("cp.async.wait_group 1;"  ::: "memory")
#define CP_WAIT0()  asm volatile("cp.async.wait_group 0;"  ::: "memory")

// mma.sync m16n8k8 tf32: D = A*B + D
__device__ __forceinline__ void mma_tf32(float c[4],
                                         uint32_t a0, uint32_t a1, uint32_t a2, uint32_t a3,
                                         uint32_t b0, uint32_t b1) {
    asm volatile(
        "mma.sync.aligned.m16n8k8.row.col.f32.tf32.tf32.f32 "
        "{%0,%1,%2,%3}, {%4,%5,%6,%7}, {%8,%9}, {%0,%1,%2,%3};"
        : "+f"(c[0]), "+f"(c[1]), "+f"(c[2]), "+f"(c[3])
        : "r"(a0), "r"(a1), "r"(a2), "r"(a3), "r"(b0), "r"(b1));
}

// ---------------- weight rounding (single launch, all 4 weights) -----------
// g_wr layout: [wqkv 3H^2 | wo H^2 | w1 4H^2 | w2 4H^2]
__global__ void round_all_kernel(const float4* __restrict__ wqkv,
                                 const float4* __restrict__ wo,
                                 const float4* __restrict__ w1,
                                 const float4* __restrict__ w2,
                                 float4* __restrict__ out)
{
    const int n4q = 3 * HH * (HH / 4);
    const int n4o = HH * (HH / 4);
    const int n4m = HH * HH;           // 4*H*H/4
    int i = blockIdx.x * blockDim.x + threadIdx.x;
    float4 v;
    if (i < n4q)                        v = wqkv[i];
    else if (i < n4q + n4o)             v = wo[i - n4q];
    else if (i < n4q + n4o + n4m)       v = w1[i - n4q - n4o];
    else                                v = w2[i - n4q - n4o - n4m];
    out[i] = make_float4(roundtf(v.x), roundtf(v.y), roundtf(v.z), roundtf(v.w));
}

// ======================= tf32 mma.sync GEMM (cp.async) =====================
// C[M,N] = A[M,K] @ W[N,K]^T + bias
// EPI: 0 bias+tf32round, 1 +res, 2 exact GELU + tf32round
#define KC          32
#define STG_FLOATS  8192
#define NSTAGE      3
#define GEMM_SMEM_BYTES (NSTAGE * STG_FLOATS * 4)   // 98304

template<int EPI>
__global__ void __launch_bounds__(256, 2)
gemm_cp(const float* __restrict__ A, const float* __restrict__ W,
        const float* __restrict__ bias, const float* __restrict__ res,
        float* __restrict__ C, int M, int N, int K)
{
    extern __shared__ float sm[];
    const uint32_t sbase = smem_u32(sm);
    const int t    = threadIdx.x;
    const int lane = t & 31;
    const int wid  = t >> 5;
    const int warp_m = wid >> 2;
    const int warp_n = wid & 3;
    const int m0 = blockIdx.y * 128;
    const int n0 = blockIdx.x * 128;

    const float* Ap = A + (size_t)m0 * K;
    const float* Wp = W + (size_t)n0 * K;

    const int cprow = t >> 3;
    const int cpc16 = t & 7;
    const int cpswz = (cpc16 ^ (cprow & 7)) * 4;

    const int g = lane >> 2;
    const int j = lane & 3;

    float acc[4][4][4];
    #pragma unroll
    for (int m = 0; m < 4; m++)
        #pragma unroll
        for (int n = 0; n < 4; n++)
            #pragma unroll
            for (int r = 0; r < 4; r++) acc[m][n][r] = 0.f;

    auto ISSUE = [&](int ch, int stage) {
        const int k0 = ch * KC;
        const uint32_t so = sbase + (uint32_t)stage * (STG_FLOATS * 4);
        #pragma unroll
        for (int i = 0; i < 4; i++) {
            const int row = cprow + i * 32;
            cp_async16(so + (uint32_t)(row * 32 + cpswz) * 4u,
                       Ap + (size_t)row * K + k0 + cpc16 * 4);
        }
        #pragma unroll
        for (int i = 0; i < 4; i++) {
            const int row = cprow + i * 32;
            cp_async16(so + (uint32_t)(4096 + row * 32 + cpswz) * 4u,
                       Wp + (size_t)row * K + k0 + cpc16 * 4);
        }
        CP_COMMIT();
    };

    auto CONSUME = [&](int stage) {
        const float* sA = sm + stage * STG_FLOATS;
        const float* sB = sA + 4096;
        #pragma unroll
        for (int kk = 0; kk < 4; kk++) {
            uint32_t af[4][4];
            uint32_t bf[4][2];
            #pragma unroll
            for (int m = 0; m < 4; m++) {
                const int rbase = warp_m * 64 + m * 16 + g;
                #pragma unroll
                for (int r = 0; r < 4; r++) {
                    const int row = rbase + (r & 1) * 8;
                    const int col = (((kk * 2 + (r >> 1)) ^ g) * 4) + j;
                    af[m][r] = __float_as_uint(sA[row * 32 + col]);
                }
            }
            #pragma unroll
            for (int n = 0; n < 4; n++) {
                const int nrow = warp_n * 32 + n * 8 + g;
                #pragma unroll
                for (int r = 0; r < 2; r++) {
                    const int col = (((kk * 2 + r) ^ g) * 4) + j;
                    bf[n][r] = __float_as_uint(sB[nrow * 32 + col]);
                }
            }
            #pragma unroll
            for (int m = 0; m < 4; m++)
                #pragma unroll
                for (int n = 0; n < 4; n++)
                    mma_tf32(acc[m][n], af[m][0], af[m][1], af[m][2], af[m][3],
                             bf[n][0], bf[n][1]);
        }
    };

    const int nch = K >> 5;
    ISSUE(0, 0);
    ISSUE(1, 1);
    int stage = 0;
    for (int ch = 0; ch < nch; ch++) {
        CP_WAIT1();
        __syncthreads();
        CONSUME(stage);
        if (ch + 2 < nch) {
            int ns = stage + 2; if (ns >= NSTAGE) ns -= NSTAGE;
            ISSUE(ch + 2, ns);
        } else {
            CP_COMMIT();
        }
        stage = (stage + 1 == NSTAGE) ? 0 : stage + 1;
    }

    const int gid = lane >> 2;
    const int tig = lane & 3;
    #pragma unroll
    for (int n = 0; n < 4; n++) {
        const int col = n0 + (warp_n * 4 + n) * 8 + tig * 2;
        const float2 bv = *(const float2*)&bias[col];
        #pragma unroll
        for (int m = 0; m < 4; m++) {
            const int rowa = m0 + (warp_m * 4 + m) * 16 + gid;
            const size_t offa = (size_t)rowa * N + col;
            const size_t offb = offa + (size_t)8 * N;
            float o0 = acc[m][n][0] + bv.x;
            float o1 = acc[m][n][1] + bv.y;
            float o2 = acc[m][n][2] + bv.x;
            float o3 = acc[m][n][3] + bv.y;
            if (EPI == 1) {
                float2 r0 = *(const float2*)&res[offa];
                float2 r1 = *(const float2*)&res[offb];
                o0 += r0.x; o1 += r0.y; o2 += r1.x; o3 += r1.y;
            }
            if (EPI == 2) {
                o0 = 0.5f * o0 * (1.0f + erff(o0 * 0.70710678118654752f));
                o1 = 0.5f * o1 * (1.0f + erff(o1 * 0.70710678118654752f));
                o2 = 0.5f * o2 * (1.0f + erff(o2 * 0.70710678118654752f));
                o3 = 0.5f * o3 * (1.0f + erff(o3 * 0.70710678118654752f));
            }
            if (EPI == 0 || EPI == 2) {   // output feeds a GEMM/attention: pre-round
                o0 = roundtf(o0); o1 = roundtf(o1);
                o2 = roundtf(o2); o3 = roundtf(o3);
            }
            *(float2*)&C[offa] = make_float2(o0, o1);
            *(float2*)&C[offb] = make_float2(o2, o3);
        }
    }
}

// ---------------- LayerNorm (stores tf32-rounded; feeds GEMMs only) --------
__global__ void ln_kernel(const float* __restrict__ x,
                          const float* __restrict__ w,
                          const float* __restrict__ b,
                          float* __restrict__ y)
{
    const int row = blockIdx.x;
    const float* xr = x + (size_t)row * HH;
    float* yr = y + (size_t)row * HH;
    const int t = threadIdx.x;

    __shared__ float red[8];
    __shared__ float bc;

    float s = 0.f;
    for (int i = t; i < HH; i += 256) s += xr[i];
    #pragma unroll
    for (int o = 16; o; o >>= 1) s += __shfl_xor_sync(0xffffffffu, s, o);
    if ((t & 31) == 0) red[t >> 5] = s;
    __syncthreads();
    if (t == 0) {
        float v = 0.f;
        #pragma unroll
        for (int i = 0; i < 8; i++) v += red[i];
        bc = v;
    }
    __syncthreads();
    const float mu = bc * (1.0f / HH);

    float vs = 0.f;
    for (int i = t; i < HH; i += 256) { float d = xr[i] - mu; vs += d * d; }
    #pragma unroll
    for (int o = 16; o; o >>= 1) vs += __shfl_xor_sync(0xffffffffu, vs, o);
    __syncthreads();
    if ((t & 31) == 0) red[t >> 5] = vs;
    __syncthreads();
    if (t == 0) {
        float v = 0.f;
        #pragma unroll
        for (int i = 0; i < 8; i++) v += red[i];
        bc = v;
    }
    __syncthreads();
    const float rstd = rsqrtf(bc * (1.0f / HH) + 1e-5f);

    for (int i = t; i < HH; i += 256)
        yr[i] = roundtf((xr[i] - mu) * rstd * w[i] + b[i]);
}

// ======================= tensor-core flash attention ========================
// grid (S/128 [reversed], B*NH), 256 threads = 8 warps x 16 q-rows.
// smem (floats): sQ 16384 (4x4096) | sK 8192 (4x2048) | sVR 8192 (4x2048)
//              | sVT 8192 (2x4096) | sP 8192 (2x4096)  = 192 KB
// K and V loaded via cp.async (coalesced); V transposed smem->smem.
#define SQ_OFF  0
#define SK_OFF  16384
#define SVR_OFF 24576
#define SVT_OFF 32768
#define SP_OFF  40960
#define ATTN_SMEM_BYTES (49152 * 4)

__global__ void __launch_bounds__(256, 1)
attn_mma_kernel(const float* __restrict__ qkv, float* __restrict__ av)
{
    extern __shared__ float sma[];
    const uint32_t sabase = smem_u32(sma);
    const int t    = threadIdx.x;
    const int lane = t & 31;
    const int wid  = t >> 5;
    const int g    = lane >> 2;
    const int j    = lane & 3;

    const int qt = (gridDim.x - 1) - blockIdx.x;   // big tiles first
    const int bh = blockIdx.y;
    const int b  = bh >> 4;
    const int h  = bh & 15;
    const int qbase = qt * 128;

    const size_t rstr = (size_t)3 * HH;
    const float* base = qkv + (size_t)b * SS * rstr;
    const int qoff = h * HD;
    const int koff = HH + h * HD;
    const int voff = 2 * HH + h * HD;

    // ---- load Q tile (128x128) into 4 swizzled chunks (4096 floats each) ----
    #pragma unroll
    for (int i = 0; i < 16; i++) {
        const int idx = t + i * 256;           // 0..4095
        const int row = idx >> 5;
        const int c4  = idx & 31;
        float4 v = *(const float4*)(base + (size_t)(qbase + row) * rstr + qoff + c4 * 4);
        const int dst = SQ_OFF + (c4 >> 3) * 4096 + row * 32 + (((c4 & 7) ^ (row & 7)) * 4);
        *(float4*)&sma[dst] = v;
    }

    const int rloc0 = wid * 16 + g;
    const int qrow0 = qbase + rloc0;
    float m0 = -1e30f, m1 = -1e30f, l0 = 0.f, l1 = 0.f;
    float o[16][4];
    #pragma unroll
    for (int n = 0; n < 16; n++)
        #pragma unroll
        for (int r = 0; r < 4; r++) o[n][r] = 0.f;

    const float rsd = 0.08838834764831845f;   // 1/sqrt(128)
    const int nkt = 2 * (qt + 1);

    for (int kt = 0; kt < nkt; kt++) {
        const int kbase = kt * 64;
        __syncthreads();   // prior tile's reads of sK/sVT/sP done; Q stores (iter 0)

        // ---- cp.async K and V (both 64x128, k-major, 4 chunks of 2048) ----
        #pragma unroll
        for (int i = 0; i < 8; i++) {
            const int idx = t + i * 256;       // 0..2047
            const int row = idx >> 5;
            const int c4  = idx & 31;
            const int off = (c4 >> 3) * 2048 + row * 32 + (((c4 & 7) ^ (row & 7)) * 4);
            const float* srcrow = base + (size_t)(kbase + row) * rstr;
            cp_async16(sabase + (uint32_t)(SK_OFF  + off) * 4u, srcrow + koff + c4 * 4);
            cp_async16(sabase + (uint32_t)(SVR_OFF + off) * 4u, srcrow + voff + c4 * 4);
        }
        CP_COMMIT();
        CP_WAIT0();
        __syncthreads();

        // ---- transpose V: sVR[k][d] -> sVT[d][k] (swizzled both sides) ----
        #pragma unroll
        for (int i = 0; i < 32; i++) {
            const int k = (lane & 3) + 4 * (i & 7) + 32 * (wid & 1);
            const int d = (lane >> 2) + 8 * (i >> 3) + 32 * (wid >> 1);
            const float v = sma[SVR_OFF + (d >> 5) * 2048 + k * 32 +
                                ((((d >> 2) & 7) ^ (k & 7)) * 4) + (d & 3)];
            const int kc = k & 31;
            sma[SVT_OFF + (k >> 5) * 4096 + d * 32 + (((kc >> 2) ^ (d & 7)) * 4) + (kc & 3)] = v;
        }

        // ---- S = Q K^T : 8 n-atoms, 16 kk steps ----
        float s[8][4];
        #pragma unroll
        for (int n = 0; n < 8; n++)
            #pragma unroll
            for (int r = 0; r < 4; r++) s[n][r] = 0.f;

        #pragma unroll
        for (int kk = 0; kk < 16; kk++) {
            const int chunk = kk >> 2, kkl = kk & 3;
            uint32_t af[4];
            #pragma unroll
            for (int r = 0; r < 4; r++) {
                const int row = rloc0 + (r & 1) * 8;
                const int col = (((kkl * 2 + (r >> 1)) ^ g) * 4) + j;
                af[r] = __float_as_uint(sma[SQ_OFF + chunk * 4096 + row * 32 + col]);
            }
            #pragma unroll
            for (int n = 0; n < 8; n++) {
                uint32_t bf[2];
                #pragma unroll
                for (int r = 0; r < 2; r++) {
                    const int col = (((kkl * 2 + r) ^ g) * 4) + j;
                    bf[r] = __float_as_uint(sma[SK_OFF + chunk * 2048 + (n * 8 + g) * 32 + col]);
                }
                mma_tf32(s[n], af[0], af[1], af[2], af[3], bf[0], bf[1]);
            }
        }

        // ---- scale + causal mask + online softmax ----
        float tm0 = -1e30f, tm1 = -1e30f;
        #pragma unroll
        for (int n = 0; n < 8; n++) {
            #pragma unroll
            for (int e = 0; e < 2; e++) {
                const int col = kbase + n * 8 + j * 2 + e;
                float v0 = s[n][e]     * rsd; if (col > qrow0)     v0 -= 1e4f;
                float v1 = s[n][2 + e] * rsd; if (col > qrow0 + 8) v1 -= 1e4f;
                s[n][e] = v0; s[n][2 + e] = v1;
                tm0 = fmaxf(tm0, v0); tm1 = fmaxf(tm1, v1);
            }
        }
        tm0 = fmaxf(tm0, __shfl_xor_sync(0xffffffffu, tm0, 1));
        tm0 = fmaxf(tm0, __shfl_xor_sync(0xffffffffu, tm0, 2));
        tm1 = fmaxf(tm1, __shfl_xor_sync(0xffffffffu, tm1, 1));
        tm1 = fmaxf(tm1, __shfl_xor_sync(0xffffffffu, tm1, 2));

        const float nm0 = fmaxf(m0, tm0), nm1 = fmaxf(m1, tm1);
        const float f0 = __expf(m0 - nm0), f1 = __expf(m1 - nm1);
        m0 = nm0; m1 = nm1;

        float rs0 = 0.f, rs1 = 0.f;
        #pragma unroll
        for (int n = 0; n < 8; n++) {
            #pragma unroll
            for (int e = 0; e < 2; e++) {
                float p0 = __expf(s[n][e]     - nm0);
                float p1 = __expf(s[n][2 + e] - nm1);
                rs0 += p0; rs1 += p1;
                s[n][e] = p0; s[n][2 + e] = p1;
            }
        }
        rs0 += __shfl_xor_sync(0xffffffffu, rs0, 1);
        rs0 += __shfl_xor_sync(0xffffffffu, rs0, 2);
        rs1 += __shfl_xor_sync(0xffffffffu, rs1, 1);
        rs1 += __shfl_xor_sync(0xffffffffu, rs1, 2);
        l0 = l0 * f0 + rs0;
        l1 = l1 * f1 + rs1;

        #pragma unroll
        for (int n = 0; n < 16; n++) {
            o[n][0] *= f0; o[n][1] *= f0;
            o[n][2] *= f1; o[n][3] *= f1;
        }

        // ---- store P (rounded) into swizzled A-tile layout ----
        #pragma unroll
        for (int n = 0; n < 8; n++) {
            #pragma unroll
            for (int e = 0; e < 2; e++) {
                const int c  = n * 8 + j * 2 + e;
                const int kc = c & 31;
                const int so = SP_OFF + (c >> 5) * 4096 + (((kc >> 2) ^ g) * 4) + (kc & 3);
                sma[so + rloc0 * 32]       = roundtf(s[n][e]);
                sma[so + (rloc0 + 8) * 32] = roundtf(s[n][2 + e]);
            }
        }
        __syncthreads();   // publish P and VT before PV

        // ---- O += P V : 16 n-atoms (d), 8 kk steps (k) ----
        #pragma unroll
        for (int kk = 0; kk < 8; kk++) {
            const int chunk = kk >> 2, kkl = kk & 3;
            uint32_t af[4];
            #pragma unroll
            for (int r = 0; r < 4; r++) {
                const int row = rloc0 + (r & 1) * 8;
                const int col = (((kkl * 2 + (r >> 1)) ^ g) * 4) + j;
                af[r] = __float_as_uint(sma[SP_OFF + chunk * 4096 + row * 32 + col]);
            }
            #pragma unroll
            for (int n = 0; n < 16; n++) {
                uint32_t bf[2];
                #pragma unroll
                for (int r = 0; r < 2; r++) {
                    const int col = (((kkl * 2 + r) ^ g) * 4) + j;
                    bf[r] = __float_as_uint(sma[SVT_OFF + chunk * 4096 + (n * 8 + g) * 32 + col]);
                }
                mma_tf32(o[n], af[0], af[1], af[2], af[3], bf[0], bf[1]);
            }
        }
    }

    // ---- epilogue: normalize, round (feeds Wo GEMM), store ----
    const float inv0 = 1.0f / l0, inv1 = 1.0f / l1;
    #pragma unroll
    for (int n = 0; n < 16; n++) {
        const int col = h * HD + n * 8 + j * 2;
        float* p0 = av + (size_t)(b * SS + qrow0) * HH + col;
        float* p1 = av + (size_t)(b * SS + qrow0 + 8) * HH + col;
        *(float2*)p0 = make_float2(roundtf(o[n][0] * inv0), roundtf(o[n][1] * inv0));
        *(float2*)p1 = make_float2(roundtf(o[n][2] * inv1), roundtf(o[n][3] * inv1));
    }
}

// ---------------- launcher --------------------------------------------------
extern "C" void kernel_launch(void* const* d_in, const int* in_sizes, int n_in,
                              void* d_out, int out_size)
{
    const float* x      = (const float*)d_in[0];
    const float* ln1_w  = (const float*)d_in[1];
    const float* ln1_b  = (const float*)d_in[2];
    const float* wqkv_w = (const float*)d_in[3];
    const float* wqkv_b = (const float*)d_in[4];
    const float* wo_w   = (const float*)d_in[5];
    const float* wo_b   = (const float*)d_in[6];
    const float* ln2_w  = (const float*)d_in[7];
    const float* ln2_b  = (const float*)d_in[8];
    const float* w1     = (const float*)d_in[9];
    const float* b1     = (const float*)d_in[10];
    const float* w2     = (const float*)d_in[11];
    const float* b2     = (const float*)d_in[12];
    float* out = (float*)d_out;

    float *ln, *qkv, *av, *h, *mid, *wr;
    cudaGetSymbolAddress((void**)&ln,  g_ln);
    cudaGetSymbolAddress((void**)&qkv, g_qkv);
    cudaGetSymbolAddress((void**)&av,  g_av);
    cudaGetSymbolAddress((void**)&h,   g_h);
    cudaGetSymbolAddress((void**)&mid, g_mid);
    cudaGetSymbolAddress((void**)&wr,  g_wr);

    float* wqkv_r = wr;
    float* wo_r   = wr + (size_t)3 * HH * HH;
    float* w1_r   = wr + (size_t)4 * HH * HH;
    float* w2_r   = wr + (size_t)8 * HH * HH;

    cudaFuncSetAttribute(attn_mma_kernel,
                         cudaFuncAttributeMaxDynamicSharedMemorySize, ATTN_SMEM_BYTES);
    cudaFuncSetAttribute(gemm_cp<0>,
                         cudaFuncAttributeMaxDynamicSharedMemorySize, GEMM_SMEM_BYTES);
    cudaFuncSetAttribute(gemm_cp<1>,
                         cudaFuncAttributeMaxDynamicSharedMemorySize, GEMM_SMEM_BYTES);
    cudaFuncSetAttribute(gemm_cp<2>,
                         cudaFuncAttributeMaxDynamicSharedMemorySize, GEMM_SMEM_BYTES);

    // 0. round all weights to tf32 in one launch (mma truncation exact)
    {
        int n4 = 12 * HH * (HH / 4);
        round_all_kernel<<<n4 / 256, 256>>>((const float4*)wqkv_w, (const float4*)wo_w,
                                            (const float4*)w1, (const float4*)w2,
                                            (float4*)wr);
    }

    // 1. ln1(x)
    ln_kernel<<<MR, 256>>>(x, ln1_w, ln1_b, ln);
    // 2. qkv = ln @ Wqkv^T + b   (rounded for attention mma)
    gemm_cp<0><<<dim3(3*HH/128, MR/128), 256, GEMM_SMEM_BYTES>>>(ln, wqkv_r, wqkv_b, nullptr, qkv,
                                                                 MR, 3*HH, HH);
    // 3. av = attention(qkv)   (tensor-core flash, rounded output)
    attn_mma_kernel<<<dim3(SS/128, BB*NHH), 256, ATTN_SMEM_BYTES>>>(qkv, av);
    // 4. h = x + av @ Wo^T + b
    gemm_cp<1><<<dim3(HH/128, MR/128), 256, GEMM_SMEM_BYTES>>>(av, wo_r, wo_b, x, h,
                                                               MR, HH, HH);
    // 5. ln2(h)
    ln_kernel<<<MR, 256>>>(h, ln2_w, ln2_b, ln);
    // 6. mid = gelu(ln @ W1^T + b1)  (rounded)
    gemm_cp<2><<<dim3(4*HH/128, MR/128), 256, GEMM_SMEM_BYTES>>>(ln, w1_r, b1, nullptr, mid,
                                                                 MR, 4*HH, HH);
    // 7. out = h + mid @ W2^T + b2
    gemm_cp<1><<<dim3(HH/128, MR/128), 256, GEMM_SMEM_BYTES>>>(mid, w2_r, b2, h, out,
                                                               MR, HH, 4*HH);
}